// round 1
// baseline (speedup 1.0000x reference)
#include <cuda_runtime.h>
#include <cuda_bf16.h>
#include <math.h>

// Accumulators: [0]=focal_sum, [1]=iou_pos_sum, [2]=npos, [3]=rcnn_sum(loss_i), [4]=pcnt_total
__device__ double g_acc[5];

__device__ __forceinline__ float block_reduce(float v, float* sh) {
    int lane = threadIdx.x & 31, wid = threadIdx.x >> 5;
    #pragma unroll
    for (int o = 16; o; o >>= 1) v += __shfl_down_sync(0xffffffffu, v, o);
    if (lane == 0) sh[wid] = v;
    __syncthreads();
    int nw = (blockDim.x + 31) >> 5;
    v = (threadIdx.x < nw) ? sh[threadIdx.x] : 0.0f;
    if (wid == 0) {
        #pragma unroll
        for (int o = 16; o; o >>= 1) v += __shfl_down_sync(0xffffffffu, v, o);
    }
    __syncthreads();   // safe shared reuse by next call
    return v;
}

__global__ void zero_kernel() {
    if (threadIdx.x < 5) g_acc[threadIdx.x] = 0.0;
}

// Part 1+2: focal loss + smooth-IoU over all B*HW anchors.
__global__ void rpn_kernel(const float2* __restrict__ cl,
                           const float4* __restrict__ re,
                           const float4* __restrict__ gr,
                           const float*  __restrict__ gt,
                           int total) {
    __shared__ float sh[32];
    int i = blockIdx.x * blockDim.x + threadIdx.x;
    float focal = 0.0f, l1 = 0.0f, np = 0.0f;
    if (i < total) {
        float2 c = cl[i];
        float g  = gt[i];
        // tgt = 1 - gt  (gt in {0,1})
        int tgt = (g > 0.0f) ? 0 : 1;
        float m   = fmaxf(c.x, c.y);
        float lse = m + logf(expf(c.x - m) + expf(c.y - m));
        float xt  = (tgt == 0) ? c.x : c.y;
        float logpt = xt - lse;
        float pt  = expf(logpt);
        float at  = (tgt == 0) ? 0.25f : 0.75f;
        float om  = 1.0f - pt;
        focal = -om * om * at * logpt;        // GAMMA=2

        float4 r = re[i], G = gr[i];
        float mn0 = fminf(r.x, G.x), mn1 = fminf(r.y, G.y);
        float mn2 = fminf(r.z, G.z), mn3 = fminf(r.w, G.w);
        float inter = (mn0 + mn2) * (mn1 + mn3);
        float ag = (G.x + G.z) * (G.y + G.w);
        float ar = (r.x + r.z) * (r.y + r.w);
        float un = ag + ar - inter + 1e-7f;
        float iou = (inter + 1.0f) / (un + 1.0f);
        if (g > 0.0f) { l1 = 1.0f - iou; np = 1.0f; }
    }
    float s0 = block_reduce(focal, sh);
    float s1 = block_reduce(l1, sh);
    float s2 = block_reduce(np, sh);
    if (threadIdx.x == 0) {
        atomicAdd(&g_acc[0], (double)s0);
        atomicAdd(&g_acc[1], (double)s1);
        atomicAdd(&g_acc[2], (double)s2);
    }
}

// Part 3: one block per batch.
__global__ void rcnn_kernel(const float*  __restrict__ cf,
                            const float*  __restrict__ op,
                            const float4* __restrict__ bb,
                            const float4* __restrict__ br,
                            const float4* __restrict__ gb,
                            int N, int K) {
    __shared__ float sh[32];
    int b = blockIdx.x;
    float4 g = gb[b];
    float area_a = (g.z - g.x) * (g.w - g.y);

    float pcnt = 0.f, ncnt = 0.f;
    float s_pp = 0.f, s_pn = 0.f, s_ng = 0.f, s_op = 0.f, s_bb = 0.f;

    size_t base = (size_t)b * (size_t)N;
    for (int n = threadIdx.x; n < N; n += blockDim.x) {
        float4 r = br[base + n];
        float lt0 = fmaxf(g.x, r.x), lt1 = fmaxf(g.y, r.y);
        float rb0 = fminf(g.z, r.z), rb1 = fminf(g.w, r.w);
        float w = fmaxf(rb0 - lt0, 0.0f), h = fmaxf(rb1 - lt1, 0.0f);
        float inter = w * h;
        float area_b = (r.z - r.x) * (r.w - r.y);
        float iou = (inter + 1e-7f) / (area_a + area_b - inter + 1e-7f);
        bool pos = (iou >= 0.5f);
        bool neg = (iou <  0.4f);
        if (pos || neg) {
            const float2* row = (const float2*)(cf + (base + (size_t)n) * (size_t)(2 * K));
            float2 c0 = row[0];
            float m   = fmaxf(c0.x, c0.y);
            float lse = m + logf(expf(c0.x - m) + expf(c0.y - m));
            if (pos) s_pp += lse - c0.x;   // -logp[...,0,0]
            if (neg) { s_pn += lse - c0.y; ncnt += 1.0f; }
            if (pos) {
                pcnt += 1.0f;
                #pragma unroll 5
                for (int k = 1; k < K; ++k) {
                    float2 ck = row[k];
                    float mk   = fmaxf(ck.x, ck.y);
                    float lsek = mk + logf(expf(ck.x - mk) + expf(ck.y - mk));
                    s_ng += lsek - ck.y;   // -logp[...,k,1]
                }
                float x = op[base + n];
                s_op += fmaxf(x, 0.0f) - x * iou + log1pf(expf(-fabsf(x)));

                float4 bx = bb[base + n];
                float l0 = fmaxf(g.x, bx.x), l1 = fmaxf(g.y, bx.y);
                float r0 = fminf(g.z, bx.z), r1 = fminf(g.w, bx.w);
                float ww = fmaxf(r0 - l0, 0.0f), hh = fmaxf(r1 - l1, 0.0f);
                float in2 = ww * hh;
                float ab2 = (bx.z - bx.x) * (bx.w - bx.y);
                float iou2 = (in2 + 1.0f) / (area_a + ab2 - in2 + 1.0f);
                s_bb += 1.0f - iou2;
            }
        }
    }

    pcnt = block_reduce(pcnt, sh);
    ncnt = block_reduce(ncnt, sh);
    s_pp = block_reduce(s_pp, sh);
    s_pn = block_reduce(s_pn, sh);
    s_ng = block_reduce(s_ng, sh);
    s_op = block_reduce(s_op, sh);
    s_bb = block_reduce(s_bb, sh);

    if (threadIdx.x == 0) {
        float l_pp = (pcnt > 0.f) ? s_pp / fmaxf(pcnt, 1.0f) : 0.0f;
        float l_pn = (ncnt > 0.f) ? s_pn / fmaxf(ncnt, 1.0f) : 0.0f;
        float l_ng = (pcnt > 0.f) ? s_ng / fmaxf(pcnt * (float)(K - 1), 1.0f) : 0.0f;
        float l_op = (pcnt > 0.f) ? s_op / fmaxf(pcnt, 1.0f) : 0.0f;
        float l_bb = (pcnt > 0.f) ? s_bb / fmaxf(pcnt, 1.0f) : 0.0f;
        float loss_i = (pcnt > 0.f) ? (l_pp + l_pn + l_ng + l_bb + l_op) : 0.0f;
        atomicAdd(&g_acc[3], (double)loss_i);
        atomicAdd(&g_acc[4], (double)pcnt);
    }
}

__global__ void finalize_kernel(float* __restrict__ out, int out_size,
                                int total_anchors, int B) {
    int i = blockIdx.x * blockDim.x + threadIdx.x;
    if (i == 0) {
        double rpn0 = g_acc[0] / (double)total_anchors;
        double np   = g_acc[2];
        double rpn1 = (np > 0.0) ? g_acc[1] / fmax(np, 1.0) : 0.0;
        double rcnn = g_acc[3] / (double)B;
        out[0] = (float)(rpn0 + rpn1 + rcnn);
        out[1] = (float)rpn0;
        out[2] = (float)rpn1;
        out[3] = (float)rcnn;
        out[4] = (float)((long long)(g_acc[4] + 0.5));
    } else if (i < out_size && i >= 5) {
        out[i] = 0.0f;
    }
}

extern "C" void kernel_launch(void* const* d_in, const int* in_sizes, int n_in,
                              void* d_out, int out_size) {
    const float* cl = (const float*)d_in[0];   // (B,HW,2)
    const float* re = (const float*)d_in[1];   // (B,HW,4)
    const float* cf = (const float*)d_in[2];   // (B,N,K,2)
    const float* op = (const float*)d_in[3];   // (B,N,1)
    const float* bb = (const float*)d_in[4];   // (B,N,4)
    const float* br = (const float*)d_in[5];   // (B,N,4)
    const float* gb = (const float*)d_in[6];   // (B,4)
    const float* gt = (const float*)d_in[7];   // (B,HW)
    // d_in[8] = gr (B,HW,4)
    const float* gr = (const float*)d_in[8];

    int B  = in_sizes[6] / 4;
    int HW = in_sizes[7] / B;
    int N  = in_sizes[3] / B;
    int K  = in_sizes[2] / (B * N * 2);
    int total = B * HW;

    zero_kernel<<<1, 32>>>();

    int blocks = (total + 255) / 256;
    rpn_kernel<<<blocks, 256>>>((const float2*)cl, (const float4*)re,
                                (const float4*)gr, gt, total);

    rcnn_kernel<<<B, 256>>>(cf, op, (const float4*)bb, (const float4*)br,
                            (const float4*)gb, N, K);

    int fblocks = (out_size + 255) / 256;
    if (fblocks < 1) fblocks = 1;
    finalize_kernel<<<fblocks, 256>>>((float*)d_out, out_size, total, B);
}

// round 2
// speedup vs baseline: 2.0047x; 2.0047x over previous
#include <cuda_runtime.h>
#include <cuda_bf16.h>
#include <math.h>

// Accumulators: [0]=focal_sum, [1]=iou_pos_sum, [2]=npos, [3]=rcnn_sum(loss_i), [4]=pcnt_total
// Zero-initialized at module load; finalize_kernel resets them after reading,
// so every kernel_launch call (and every graph replay) starts from zero.
__device__ double g_acc[5];

#define RPN_BLOCKS 1184   // 148 SMs * 8

__device__ __forceinline__ float blk_reduce(float v, float* sh) {
    int lane = threadIdx.x & 31, wid = threadIdx.x >> 5;
    #pragma unroll
    for (int o = 16; o; o >>= 1) v += __shfl_down_sync(0xffffffffu, v, o);
    if (lane == 0) sh[wid] = v;
    __syncthreads();
    int nw = (blockDim.x + 31) >> 5;
    v = (threadIdx.x < nw) ? sh[threadIdx.x] : 0.0f;
    if (wid == 0) {
        #pragma unroll
        for (int o = 16; o; o >>= 1) v += __shfl_down_sync(0xffffffffu, v, o);
    }
    __syncthreads();
    return v;
}

// softplus(d) = max(d,0) + log1p(exp(-|d|)); shared t,l give both signs cheaply.

__global__ __launch_bounds__(256)
void fused_kernel(const float2* __restrict__ cl,
                  const float4* __restrict__ re,
                  const float4* __restrict__ gr,
                  const float*  __restrict__ gt,
                  const float*  __restrict__ cf,
                  const float*  __restrict__ op,
                  const float4* __restrict__ bb,
                  const float4* __restrict__ br,
                  const float4* __restrict__ gb,
                  int total, int N, int K, int B) {
    __shared__ float sh[32];

    if (blockIdx.x < (unsigned)B) {
        // ---------------- RCNN: one block per batch (first wave, overlaps rpn) ----
        int b = blockIdx.x;
        float4 g = gb[b];
        float area_a = (g.z - g.x) * (g.w - g.y);

        float pcnt = 0.f, ncnt = 0.f;
        float s_pp = 0.f, s_pn = 0.f, s_ng = 0.f, s_op = 0.f, s_bb = 0.f;

        size_t base = (size_t)b * (size_t)N;
        int halfK = K >> 1;
        for (int n = threadIdx.x; n < N; n += blockDim.x) {
            float4 r = br[base + n];
            float lt0 = fmaxf(g.x, r.x), lt1 = fmaxf(g.y, r.y);
            float rb0 = fminf(g.z, r.z), rb1 = fminf(g.w, r.w);
            float w = fmaxf(rb0 - lt0, 0.0f), h = fmaxf(rb1 - lt1, 0.0f);
            float inter = w * h;
            float area_b = (r.z - r.x) * (r.w - r.y);
            float iou = __fdividef(inter + 1e-7f, area_a + area_b - inter + 1e-7f);
            bool pos = (iou >= 0.5f);
            bool neg = (iou <  0.4f);
            if (pos || neg) {
                const float4* rp = reinterpret_cast<const float4*>(cf)
                                 + (base + (size_t)n) * (size_t)halfK;
                float4 v0 = rp[0];
                // class 0 pair (v0.x, v0.y):  -logp0 = softplus(y-x), -logp1 = softplus(x-y)
                float d0 = v0.x - v0.y;
                float t0 = __expf(-fabsf(d0));
                float l0 = __logf(1.0f + t0);
                if (pos) s_pp += fmaxf(-d0, 0.0f) + l0;
                if (neg) { s_pn += fmaxf(d0, 0.0f) + l0; ncnt += 1.0f; }
                if (pos) {
                    pcnt += 1.0f;
                    // k=1 from (v0.z, v0.w): -logp[k,1] = softplus(z-w)
                    {
                        float d = v0.z - v0.w;
                        s_ng += fmaxf(d, 0.0f) + __logf(1.0f + __expf(-fabsf(d)));
                    }
                    #pragma unroll 7
                    for (int j = 1; j < halfK; ++j) {
                        float4 v = rp[j];
                        float da = v.x - v.y;
                        s_ng += fmaxf(da, 0.0f) + __logf(1.0f + __expf(-fabsf(da)));
                        float db = v.z - v.w;
                        s_ng += fmaxf(db, 0.0f) + __logf(1.0f + __expf(-fabsf(db)));
                    }
                    float x = op[base + n];
                    s_op += fmaxf(x, 0.0f) - x * iou
                          + __logf(1.0f + __expf(-fabsf(x)));

                    float4 bx = bb[base + n];
                    float l0b = fmaxf(g.x, bx.x), l1b = fmaxf(g.y, bx.y);
                    float r0b = fminf(g.z, bx.z), r1b = fminf(g.w, bx.w);
                    float ww = fmaxf(r0b - l0b, 0.0f), hh = fmaxf(r1b - l1b, 0.0f);
                    float in2 = ww * hh;
                    float ab2 = (bx.z - bx.x) * (bx.w - bx.y);
                    float iou2 = __fdividef(in2 + 1.0f, area_a + ab2 - in2 + 1.0f);
                    s_bb += 1.0f - iou2;
                }
            }
        }

        pcnt = blk_reduce(pcnt, sh);
        ncnt = blk_reduce(ncnt, sh);
        s_pp = blk_reduce(s_pp, sh);
        s_pn = blk_reduce(s_pn, sh);
        s_ng = blk_reduce(s_ng, sh);
        s_op = blk_reduce(s_op, sh);
        s_bb = blk_reduce(s_bb, sh);

        if (threadIdx.x == 0) {
            float l_pp = (pcnt > 0.f) ? s_pp / fmaxf(pcnt, 1.0f) : 0.0f;
            float l_pn = (ncnt > 0.f) ? s_pn / fmaxf(ncnt, 1.0f) : 0.0f;
            float l_ng = (pcnt > 0.f) ? s_ng / fmaxf(pcnt * (float)(K - 1), 1.0f) : 0.0f;
            float l_op = (pcnt > 0.f) ? s_op / fmaxf(pcnt, 1.0f) : 0.0f;
            float l_bb = (pcnt > 0.f) ? s_bb / fmaxf(pcnt, 1.0f) : 0.0f;
            float loss_i = (pcnt > 0.f) ? (l_pp + l_pn + l_ng + l_bb + l_op) : 0.0f;
            atomicAdd(&g_acc[3], (double)loss_i);
            atomicAdd(&g_acc[4], (double)pcnt);
        }
    } else {
        // ---------------- RPN: grid-stride over B*HW anchors ----------------------
        int tid = (blockIdx.x - B) * blockDim.x + threadIdx.x;
        int stride = RPN_BLOCKS * blockDim.x;
        float a0 = 0.f, a1 = 0.f, a2 = 0.f;
        #pragma unroll 4
        for (int i = tid; i < total; i += stride) {
            float2 c = cl[i];
            float gv = gt[i];
            float4 r = re[i], G = gr[i];

            bool posg = gv > 0.0f;
            // focal: tgt = posg ? 0 : 1 ; s = x_tgt - x_other
            float s = posg ? (c.x - c.y) : (c.y - c.x);
            float t = __expf(-fabsf(s));
            float l = __logf(1.0f + t);
            float logpt = fminf(s, 0.0f) - l;        // log softmax of target
            float pt = __expf(logpt);
            float at = posg ? 0.25f : 0.75f;
            float om = 1.0f - pt;
            a0 += -om * om * at * logpt;

            float mn0 = fminf(r.x, G.x), mn1 = fminf(r.y, G.y);
            float mn2 = fminf(r.z, G.z), mn3 = fminf(r.w, G.w);
            float inter = (mn0 + mn2) * (mn1 + mn3);
            float ag = (G.x + G.z) * (G.y + G.w);
            float ar = (r.x + r.z) * (r.y + r.w);
            float un = ag + ar - inter + 1e-7f;
            float iou = __fdividef(inter + 1.0f, un + 1.0f);
            if (posg) { a1 += 1.0f - iou; a2 += 1.0f; }
        }
        a0 = blk_reduce(a0, sh);
        a1 = blk_reduce(a1, sh);
        a2 = blk_reduce(a2, sh);
        if (threadIdx.x == 0) {
            atomicAdd(&g_acc[0], (double)a0);
            atomicAdd(&g_acc[1], (double)a1);
            atomicAdd(&g_acc[2], (double)a2);
        }
    }
}

__global__ void finalize_kernel(float* __restrict__ out, int out_size,
                                int total_anchors, int B) {
    int i = blockIdx.x * blockDim.x + threadIdx.x;
    if (i == 0) {
        double rpn0 = g_acc[0] / (double)total_anchors;
        double np   = g_acc[2];
        double rpn1 = (np > 0.0) ? g_acc[1] / fmax(np, 1.0) : 0.0;
        double rcnn = g_acc[3] / (double)B;
        out[0] = (float)(rpn0 + rpn1 + rcnn);
        out[1] = (float)rpn0;
        out[2] = (float)rpn1;
        out[3] = (float)rcnn;
        out[4] = (float)((long long)(g_acc[4] + 0.5));
        // reset accumulators for the next call / graph replay
        g_acc[0] = 0.0; g_acc[1] = 0.0; g_acc[2] = 0.0;
        g_acc[3] = 0.0; g_acc[4] = 0.0;
    } else if (i < out_size && i >= 5) {
        out[i] = 0.0f;
    }
}

extern "C" void kernel_launch(void* const* d_in, const int* in_sizes, int n_in,
                              void* d_out, int out_size) {
    const float* cl = (const float*)d_in[0];   // (B,HW,2)
    const float* re = (const float*)d_in[1];   // (B,HW,4)
    const float* cf = (const float*)d_in[2];   // (B,N,K,2)
    const float* op = (const float*)d_in[3];   // (B,N,1)
    const float* bb = (const float*)d_in[4];   // (B,N,4)
    const float* br = (const float*)d_in[5];   // (B,N,4)
    const float* gb = (const float*)d_in[6];   // (B,4)
    const float* gt = (const float*)d_in[7];   // (B,HW)
    const float* gr = (const float*)d_in[8];   // (B,HW,4)

    int B  = in_sizes[6] / 4;
    int HW = in_sizes[7] / B;
    int N  = in_sizes[3] / B;
    int K  = in_sizes[2] / (B * N * 2);
    int total = B * HW;

    fused_kernel<<<B + RPN_BLOCKS, 256>>>(
        (const float2*)cl, (const float4*)re, (const float4*)gr, gt,
        cf, op, (const float4*)bb, (const float4*)br, (const float4*)gb,
        total, N, K, B);

    int fblocks = (out_size + 255) / 256;
    if (fblocks < 1) fblocks = 1;
    finalize_kernel<<<fblocks, 256>>>((float*)d_out, out_size, total, B);
}